// round 4
// baseline (speedup 1.0000x reference)
#include <cuda_runtime.h>

// Cubic B-spline prefilter (Unser), DCT-II mirror boundaries, as a truncated
// symmetric FIR: h[k] = sqrt(3) * p^|k|, p = sqrt(3)-2, radius 8 (17 taps).
// Pass 1: fused W+H. W-filter reads gmem directly (per-thread contiguous
//         128B-vector loads), writes smem; H-filter reads smem, writes gmem.
// Pass 2: D axis, in place.

#define NAX   192
#define KR    8
#define NT    (2*KR + 1)        // 17 taps
#define TW    64                // strip output width
#define P2    (TW + 1)          // s2 pitch = 65 (conflict-free columns)
#define SEGH  24                // H-phase outputs/thread
#define WLH   (SEGH + 2*KR)     // 40
#define SEGD  24
#define WLD   (SEGD + 2*KR)     // 40
#define TPB   256

// taps T[k] = sqrt(3)*p^|k-8| as compile-time floats -> FFMA-imm in SASS (rt=1)
#define DECL_TAPS const float T[NT] = { \
     4.6023585e-05f, -1.7176230e-04f,  6.4102556e-04f, -2.3923386e-03f, \
     8.9283341e-03f, -3.3320997e-02f,  1.2435565e-01f, -4.6410161e-01f, \
     1.7320508e+00f, -4.6410161e-01f,  1.2435565e-01f, -3.3320997e-02f, \
     8.9283341e-03f, -2.3923386e-03f,  6.4102556e-04f, -1.7176230e-04f, \
     4.6023585e-05f }

__device__ __forceinline__ int mirror_idx(int i) {
    i = (i < 0) ? (-1 - i) : i;                  // half-sample left reflect
    return (i >= NAX) ? (2 * NAX - 1 - i) : i;   // half-sample right reflect
}

// ---------------------------------------------------------------------------
// Fused W+H pass on a 192(h) x 64(w) strip. No input staging buffer:
// W tasks pull their 32-float windows straight from gmem (8x LDG.128 each).
// Single barrier between W (writes s2) and H (reads s2, STGs results).
// ---------------------------------------------------------------------------
__global__ __launch_bounds__(TPB, 4) void kWH(const float* __restrict__ in,
                                              float* __restrict__ out) {
    extern __shared__ float s2[];   // [192][P2]

    const int tid   = threadIdx.x;
    const int strip = blockIdx.x % (NAX / TW);   // 3 strips; adjacent -> L2 halo reuse
    const int slice = blockIdx.x / (NAX / TW);
    const int base  = slice * (NAX * NAX);
    const int wbase = strip * TW;

    DECL_TAPS;

    // ---- W filter: 768 tasks = (row 0..191) x (seg 0..3 of 16 outputs)
#pragma unroll
    for (int r = 0; r < 3; ++r) {
        const int t   = tid + TPB * r;
        const int row = t % NAX;
        const int seg = t / NAX;                 // 0..3
        const int c0  = wbase + seg * 16 - KR;   // first window col (global)

        float win[32];
        if (c0 >= 0 && c0 <= NAX - 32) {
            // fast path: 8 aligned float4 loads (full 128B sectors per lane)
            const float4* p = (const float4*)(in + base + row * NAX + c0);
#pragma unroll
            for (int q = 0; q < 8; ++q) {
                float4 v = p[q];
                win[4 * q + 0] = v.x; win[4 * q + 1] = v.y;
                win[4 * q + 2] = v.z; win[4 * q + 3] = v.w;
            }
        } else {
            // edge path (strip 0 seg 0 / strip 2 seg 3): mirrored scalar loads
            const float* rp = in + base + row * NAX;
#pragma unroll
            for (int m = 0; m < 32; ++m) win[m] = rp[mirror_idx(c0 + m)];
        }

        float* dst = &s2[row * P2 + seg * 16];   // lanes: consecutive rows -> distinct banks
#pragma unroll
        for (int j = 0; j < 16; ++j) {
            float acc = 0.0f;
#pragma unroll
            for (int k = 0; k < NT; ++k) acc = fmaf(T[k], win[j + k], acc);
            dst[j] = acc;
        }
    }
    __syncthreads();

    // ---- H filter: 512 tasks = (w 0..63) x (hseg 0..7 of 24 outputs)
#pragma unroll
    for (int r = 0; r < 2; ++r) {
        const int t    = tid + TPB * r;
        const int w    = t & (TW - 1);
        const int hseg = t / TW;                 // 0..7
        const int h0   = hseg * SEGH;

        float win[WLH];
#pragma unroll
        for (int m = 0; m < WLH; ++m)
            win[m] = s2[mirror_idx(h0 - KR + m) * P2 + w];  // lane = w -> conflict-free

        float* o = out + base + wbase + w;
#pragma unroll
        for (int j = 0; j < SEGH; ++j) {
            float acc = 0.0f;
#pragma unroll
            for (int k = 0; k < NT; ++k) acc = fmaf(T[k], win[j + k], acc);
            o[(h0 + j) * NAX] = acc;             // 128B coalesced per j
        }
    }
}

// ---------------------------------------------------------------------------
// D pass (stride 192*192), in place. Tile: 192(d) x 32(w).  (unchanged)
// ---------------------------------------------------------------------------
__global__ __launch_bounds__(TPB, 5) void kD(float* buf) {
    __shared__ float s[NAX][32];
    const int tid = threadIdx.x;
    const int c   = blockIdx.x % (NAX / 32);
    const int tt  = blockIdx.x / (NAX / 32);
    const int b   = tt / NAX;
    const int hh  = tt % NAX;
    const int base = b * (NAX * NAX * NAX) + hh * NAX + c * 32;

    const int w  = tid & 31;
    const int a4 = tid >> 5;
#pragma unroll
    for (int k = 0; k < NAX / 8; ++k)   // 24 outstanding LDG/thread
        s[a4 + 8 * k][w] = buf[base + (a4 + 8 * k) * (NAX * NAX) + w];
    __syncthreads();

    DECL_TAPS;
    const int a0 = (tid >> 5) * SEGD;
    float win[WLD];
#pragma unroll
    for (int m = 0; m < WLD; ++m)
        win[m] = s[mirror_idx(a0 - KR + m)][w];

#pragma unroll
    for (int j = 0; j < SEGD; ++j) {
        float acc = 0.0f;
#pragma unroll
        for (int k = 0; k < NT; ++k) acc = fmaf(T[k], win[j + k], acc);
        buf[base + (a0 + j) * (NAX * NAX) + w] = acc;     // 128B coalesced per j
    }
}

extern "C" void kernel_launch(void* const* d_in, const int* in_sizes, int n_in,
                              void* d_out, int out_size) {
    const float* x = (const float*)d_in[0];
    float* y = (float*)d_out;

    const int B = 8;   // 4 batch * 2 channel
    const int smemWH = NAX * P2 * (int)sizeof(float);   // 49920 B

    static int attr_set = 0;
    if (!attr_set) {
        cudaFuncSetAttribute(kWH, cudaFuncAttributeMaxDynamicSharedMemorySize, smemWH);
        attr_set = 1;
    }

    kWH<<<B * NAX * (NAX / TW), TPB, smemWH>>>(x, y);  // W+H fused: d_in -> d_out
    kD<<<B * NAX * (NAX / 32), TPB>>>(y);              // D axis: in place
}

// round 5
// speedup vs baseline: 1.6358x; 1.6358x over previous
#include <cuda_runtime.h>

// Cubic B-spline prefilter (Unser), DCT-II mirror boundaries, as a truncated
// symmetric FIR: h[k] = sqrt(3) * p^|k|, p = sqrt(3)-2, radius 8 (17 taps).
// Pass 1: fused W+H on 192(h) x 32(w) strips, SINGLE smem buffer:
//         W filter runs in place via a 17-deep register delay line.
// Pass 2: D axis, in place.

#define NAX   192
#define KR    8
#define NT    (2*KR + 1)        // 17 taps
#define TW    32                // strip output width
#define LC    (TW + 2*KR)       // 48 loaded cols (halo +-8)
#define P1    49                // smem pitch (odd -> conflict-free both ways)
#define SEGH  16                // H-phase outputs/thread
#define WLH   (SEGH + 2*KR)     // 32
#define SEGD  24
#define WLD   (SEGD + 2*KR)     // 40
#define TPBF  192
#define TPBD  256

// taps T[k] = sqrt(3)*p^|k-8| as compile-time floats -> FFMA-imm in SASS (rt=1)
#define DECL_TAPS const float T[NT] = { \
     4.6023585e-05f, -1.7176230e-04f,  6.4102556e-04f, -2.3923386e-03f, \
     8.9283341e-03f, -3.3320997e-02f,  1.2435565e-01f, -4.6410161e-01f, \
     1.7320508e+00f, -4.6410161e-01f,  1.2435565e-01f, -3.3320997e-02f, \
     8.9283341e-03f, -2.3923386e-03f,  6.4102556e-04f, -1.7176230e-04f, \
     4.6023585e-05f }

__device__ __forceinline__ int mirror_idx(int i) {
    i = (i < 0) ? (-1 - i) : i;                  // half-sample left reflect
    return (i >= NAX) ? (2 * NAX - 1 - i) : i;   // half-sample right reflect
}

// ---------------------------------------------------------------------------
// Fused W+H pass, one 192 x 32 strip per block, one 192x49 smem buffer.
// Phase 1: load 192x48 (w-halo mirrored).
// Phase 2: W filter in place (thread = row, register delay line).
// Phase 3: H filter on cols [8,40), direct coalesced STG.
// ---------------------------------------------------------------------------
__global__ __launch_bounds__(TPBF, 5) void kWH(const float* __restrict__ in,
                                               float* __restrict__ out) {
    extern __shared__ float s[];   // [192][P1]

    const int tid   = threadIdx.x;              // 0..191
    const int strip = blockIdx.x % (NAX / TW);  // 6 strips; adjacent -> L2 halo reuse
    const int slice = blockIdx.x / (NAX / TW);
    const int base  = slice * (NAX * NAX);
    const int wbase = strip * TW;

    // ---- load 192 x 48 (coalesced LDG, independent -> high MLP)
#pragma unroll
    for (int k = 0; k < (NAX * LC) / TPBF; ++k) {   // 48 iterations
        int i   = tid + TPBF * k;
        int row = i / LC;
        int c   = i - row * LC;
        s[row * P1 + c] = in[base + row * NAX + mirror_idx(wbase - KR + c)];
    }
    __syncthreads();

    DECL_TAPS;

    // ---- W filter in place: thread owns row `tid`.
    // Emit out[j] (smem col j+8) after reading input col j+16; all future
    // uses of overwritten inputs live in the register window win[0..16].
    {
        float* rp = &s[tid * P1];   // lanes: stride-49 -> conflict-free
        float win[NT];
#pragma unroll
        for (int m = 0; m < NT - 1; ++m) win[m] = rp[m];   // preload cols 0..15
#pragma unroll
        for (int j = 0; j < TW; ++j) {
            win[NT - 1] = rp[j + 2 * KR];                  // read col j+16
            float acc = 0.0f;
#pragma unroll
            for (int k = 0; k < NT; ++k) acc = fmaf(T[k], win[k], acc);
            rp[j + KR] = acc;                              // write col j+8
#pragma unroll
            for (int m = 0; m < NT - 1; ++m) win[m] = win[m + 1];  // reg rotate
        }
    }
    __syncthreads();

    // ---- H filter: 384 tasks = (w 0..31) x (hseg 0..11 of 16 outputs)
#pragma unroll
    for (int r = 0; r < 2; ++r) {
        const int t    = tid + TPBF * r;
        const int w    = t & (TW - 1);
        const int hseg = t >> 5;                 // 0..11
        const int h0   = hseg * SEGH;

        float win[WLH];
#pragma unroll
        for (int m = 0; m < WLH; ++m)
            win[m] = s[mirror_idx(h0 - KR + m) * P1 + KR + w];  // lane = w -> conflict-free

        float* o = out + base + wbase + w;
#pragma unroll
        for (int j = 0; j < SEGH; ++j) {
            float acc = 0.0f;
#pragma unroll
            for (int k = 0; k < NT; ++k) acc = fmaf(T[k], win[j + k], acc);
            o[(h0 + j) * NAX] = acc;             // 128B coalesced per j
        }
    }
}

// ---------------------------------------------------------------------------
// D pass (stride 192*192), in place. Tile: 192(d) x 32(w).  (unchanged)
// ---------------------------------------------------------------------------
__global__ __launch_bounds__(TPBD, 5) void kD(float* buf) {
    __shared__ float s[NAX][32];
    const int tid = threadIdx.x;
    const int c   = blockIdx.x % (NAX / 32);
    const int tt  = blockIdx.x / (NAX / 32);
    const int b   = tt / NAX;
    const int hh  = tt % NAX;
    const int base = b * (NAX * NAX * NAX) + hh * NAX + c * 32;

    const int w  = tid & 31;
    const int a4 = tid >> 5;
#pragma unroll
    for (int k = 0; k < NAX / 8; ++k)   // 24 outstanding LDG/thread
        s[a4 + 8 * k][w] = buf[base + (a4 + 8 * k) * (NAX * NAX) + w];
    __syncthreads();

    DECL_TAPS;
    const int a0 = (tid >> 5) * SEGD;
    float win[WLD];
#pragma unroll
    for (int m = 0; m < WLD; ++m)
        win[m] = s[mirror_idx(a0 - KR + m)][w];

#pragma unroll
    for (int j = 0; j < SEGD; ++j) {
        float acc = 0.0f;
#pragma unroll
        for (int k = 0; k < NT; ++k) acc = fmaf(T[k], win[j + k], acc);
        buf[base + (a0 + j) * (NAX * NAX) + w] = acc;     // 128B coalesced per j
    }
}

extern "C" void kernel_launch(void* const* d_in, const int* in_sizes, int n_in,
                              void* d_out, int out_size) {
    const float* x = (const float*)d_in[0];
    float* y = (float*)d_out;

    const int B = 8;   // 4 batch * 2 channel
    const int smemWH = NAX * P1 * (int)sizeof(float);   // 37632 B

    static int attr_set = 0;
    if (!attr_set) {
        cudaFuncSetAttribute(kWH, cudaFuncAttributeMaxDynamicSharedMemorySize, smemWH);
        attr_set = 1;
    }

    kWH<<<B * NAX * (NAX / TW), TPBF, smemWH>>>(x, y);  // W+H fused: d_in -> d_out
    kD<<<B * NAX * (NAX / 32), TPBD>>>(y);              // D axis: in place
}